// round 17
// baseline (speedup 1.0000x reference)
#include <cuda_runtime.h>
#include <cuda_fp16.h>
#include <cstdint>

#define HW     56
#define CIN    128
#define COUT   128
#define NB     5
#define WELEMS (COUT * CIN * 9)

// ---------------- device scratch (no allocs allowed) ----------------
__device__ float g_part[160];
// effective weights, fp16, pre-swizzled ldmatrix-ready 8KB tiles:
// [tap][chunk][nhalf][k=64][n=64] ; byte off in tile = k*128 + ((n*2)^((k&7)*16))
__device__ __align__(256) __half g_wB[9 * 2 * 2 * 64 * 64];

// ---------------- helpers ----------------
static __device__ __forceinline__ uint32_t smem_u32(const void* p) {
    uint32_t a;
    asm("{ .reg .u64 t; cvta.to.shared.u64 t, %1; cvt.u32.u64 %0, t; }" : "=r"(a) : "l"(p));
    return a;
}

static __device__ __forceinline__ void mma16816(float* c, const uint32_t* a,
                                                uint32_t b0, uint32_t b1) {
    asm volatile(
        "mma.sync.aligned.m16n8k16.row.col.f32.f16.f16.f32 "
        "{%0,%1,%2,%3}, {%4,%5,%6,%7}, {%8,%9}, {%0,%1,%2,%3};"
        : "+f"(c[0]), "+f"(c[1]), "+f"(c[2]), "+f"(c[3])
        : "r"(a[0]), "r"(a[1]), "r"(a[2]), "r"(a[3]), "r"(b0), "r"(b1));
}

static __device__ __forceinline__ void ldsm4t(uint32_t* r, uint32_t addr) {
    asm volatile("ldmatrix.sync.aligned.m8n8.x4.trans.shared.b16 {%0,%1,%2,%3}, [%4];"
                 : "=r"(r[0]), "=r"(r[1]), "=r"(r[2]), "=r"(r[3])
                 : "r"(addr));
}

// ====== prep 1: partial sums of |w| (160 blocks = 5 bases x 32 segs, float4) ======
__global__ void mean_abs_part_kernel(const float* __restrict__ w) {
    int n = blockIdx.x >> 5, seg = blockIdx.x & 31;
    const float4* wn = (const float4*)(w + (size_t)n * WELEMS + seg * (WELEMS / 32));
    float s = 0.f;
#pragma unroll 4
    for (int i = threadIdx.x; i < WELEMS / 128; i += 256) {
        float4 f = __ldg(&wn[i]);
        s += fabsf(f.x) + fabsf(f.y) + fabsf(f.z) + fabsf(f.w);
    }
    __shared__ float red[256];
    red[threadIdx.x] = s;
    __syncthreads();
    for (int off = 128; off > 0; off >>= 1) {
        if (threadIdx.x < off) red[threadIdx.x] += red[threadIdx.x + off];
        __syncthreads();
    }
    if (threadIdx.x == 0) g_part[blockIdx.x] = red[0];
}

// ====== prep 2: effective weight -> swizzled fp16 B tiles (means inlined) ======
// one thread per (o-pair, i): coalesced reads; paired uint32 (o,o+1) writes
__global__ void build_wB_kernel(const float* __restrict__ w,
                                const float* __restrict__ scales) {
    int idx = blockIdx.x * 256 + threadIdx.x;   // op*128 + i, [0,8192)
    float m[NB];
#pragma unroll
    for (int n = 0; n < NB; n++) {
        float s = 0.f;
#pragma unroll
        for (int j = 0; j < 32; j++) s += __ldg(&g_part[n * 32 + j]);
        m[n] = s / (float)WELEMS;
    }
    int op = idx >> 7;            // o-pair 0..63
    int i = idx & 127;            // cin
    int o0 = op * 2;
    float v0[9], v1[9];
#pragma unroll
    for (int j = 0; j < 9; j++) { v0[j] = 0.f; v1[j] = 0.f; }
#pragma unroll
    for (int n = 0; n < NB; n++) {
        const float* wp0 = w + (((size_t)n * COUT + o0) * CIN + i) * 9;
        const float* wp1 = wp0 + (size_t)CIN * 9;
        float sm = __ldg(&scales[n]) * m[n];
#pragma unroll
        for (int j = 0; j < 9; j++) {
            float w0 = __ldg(&wp0[j]);
            float w1 = __ldg(&wp1[j]);
            v0[j] += sm * ((w0 > 0.f) ? 1.f : ((w0 < 0.f) ? -1.f : 0.f));
            v1[j] += sm * ((w1 > 0.f) ? 1.f : ((w1 < 0.f) ? -1.f : 0.f));
        }
    }
    int chunk = i >> 6;
    int kl = i & 63;
    int nh = o0 >> 6;             // n-half 0/1
    int n2 = o0 & 63;             // even
    // byte off within 8KB tile; n2 even -> (o0,o0+1) share one aligned uint32
    uint32_t boff = (uint32_t)kl * 128 + (((uint32_t)n2 * 2) ^ (((uint32_t)kl & 7) * 16));
    uint32_t* wB32 = (uint32_t*)g_wB;
#pragma unroll
    for (int kidx = 0; kidx < 9; kidx++) {
        size_t tileb = (size_t)(((kidx * 2 + chunk) * 2 + nh)) * 8192;  // bytes
        __half h0 = __float2half_rn(v0[kidx]);
        __half h1 = __float2half_rn(v1[kidx]);
        uint32_t pk = (uint32_t)__half_as_ushort(h0) |
                      ((uint32_t)__half_as_ushort(h1) << 16);
        wB32[(tileb + boff) >> 2] = pk;
    }
}

// == conv kernel: HMMA implicit GEMM, 512 thr, M128 x N64 tile, 3 CTA/SM target ==
// dyn smem (bytes):
//   [0]      B tiles: 4 bufs x 8192 = 32768
//   [32768]  slab: 32 k-pair rows x 232 words + 16 pad = 7456 words = 29824
#define SM_B       0u
#define SM_SLAB    32768u
#define SMEM_TOTAL (32768 + 7456 * 4)   // 62592

static __device__ __forceinline__ void issue_B(uint32_t sdst, const uint8_t* gsrc, int tid) {
    asm volatile("cp.async.cg.shared.global [%0], [%1], 16;"
                 :: "r"(sdst + (uint32_t)tid * 16u), "l"(gsrc + tid * 16));
    asm volatile("cp.async.commit_group;" ::: "memory");
}

__global__ void __launch_bounds__(512, 3)
conv_kernel(const float* __restrict__ x, float* __restrict__ out) {
    extern __shared__ __align__(16) uint8_t smem[];
    const uint32_t sb = smem_u32(smem);
    uint32_t* slabh = (uint32_t*)(smem + SM_SLAB);

    const int tid = threadIdx.x;
    const int lane = tid & 31, wid = tid >> 5;
    const int g = lane >> 2, tig = lane & 3;
    const int mw = wid & 7;          // m block of 16  (8 blocks -> M=128)
    const int nw = wid >> 3;         // n quarter of 32 (2 -> N=64 per CTA)
    const int mf = mw * 16;
    const int r0 = blockIdx.x * 2;   // first output row
    const int b = blockIdx.y;
    const int nh = blockIdx.z;       // n-half of cout

    // zero slab pad (finite garbage only)
    if (tid < 16) slabh[7440 + tid] = 0;

    float acc[4][4];
#pragma unroll
    for (int j = 0; j < 4; j++)
#pragma unroll
        for (int q = 0; q < 4; q++) acc[j][q] = 0.f;

    // B ldmatrix lane constants — s-invariant up to +s*2048
    const int krow_l = (lane & 7) + ((lane & 8) ? 8 : 0);
    const int nsel = ((lane & 16) ? 8 : 0) + nw * 32;
    uint32_t bnp[2];
#pragma unroll
    for (int np = 0; np < 2; np++)
        bnp[np] = (uint32_t)krow_l * 128u +
                  ((((uint32_t)(nsel + np * 16)) * 2u) ^ (((uint32_t)krow_l & 7u) * 16u));

    const uint8_t* wBb = (const uint8_t*)g_wB + (size_t)nh * 8192;

    // pre-issue B tiles for iters 0 and 1 (tap0/ch0, tap1/ch0); tile stride 2*8192
    issue_B(sb + SM_B, wBb, tid);
    issue_B(sb + SM_B + 8192u, wBb + 2 * 16384, tid);

#pragma unroll 1
    for (int iter = 0; iter < 18; iter++) {
        const int chunk = (iter >= 9) ? 1 : 0;
        const int kidx = iter - 9 * chunk;
        const int ky = kidx / 3;
        const int kx = kidx - 3 * ky;

        if ((iter & 1) == 0) {
            __syncthreads();   // one block-wide ordering point per 2 iters
            if (iter + 2 < 18) {
                int n2i = iter + 2;
                int nc2 = (n2i >= 9) ? 1 : 0;
                int nk2 = n2i - 9 * nc2;
                issue_B(sb + SM_B + (uint32_t)((n2i & 3) * 8192),
                        wBb + (size_t)(nk2 * 2 + nc2) * 16384, tid);
                if (iter + 3 < 18) {
                    int n3 = iter + 3;
                    int nc3 = (n3 >= 9) ? 1 : 0;
                    int nk3 = n3 - 9 * nc3;
                    issue_B(sb + SM_B + (uint32_t)((n3 & 3) * 8192),
                            wBb + (size_t)(nk3 * 2 + nc3) * 16384, tid);
                    asm volatile("cp.async.wait_group 2;" ::: "memory");
                } else {
                    asm volatile("cp.async.wait_group 1;" ::: "memory");
                }
            } else {
                asm volatile("cp.async.wait_group 0;" ::: "memory");
            }
        }

        // stage x slab for this 64-channel chunk (coalesced; pad = 1.0)
        if (kidx == 0) {
            if (iter == 9) __syncthreads();   // all warps done reading chunk-0 slab
            const float* xp = x + ((size_t)b * CIN + chunk * 64) * (HW * HW);
#pragma unroll 1
            for (int idx = tid; idx < 64 * 232; idx += 512) {
                int ch = idx / 232;
                int pos = idx - ch * 232;
                int r = pos / 58;
                int c = pos - r * 58;
                int gy = r0 - 1 + r, gx = c - 1;
                float v = 1.0f;
                if ((unsigned)gy < HW && (unsigned)gx < HW)
                    v = __ldg(xp + ch * (HW * HW) + gy * HW + gx);
                int wd = (ch >> 1) * 232 + pos;
                ((__half*)slabh)[wd * 2 + (ch & 1)] = __float2half_rn(v);
            }
            __syncthreads();                  // slab visible before compute
        }

        const uint32_t cur = sb + SM_B + (uint32_t)((iter & 3) * 8192);
#pragma unroll
        for (int s = 0; s < 4; s++) {
            // ---- A fragment via plain LDS.32 from k-pair-packed slab ----
            const int pos0 = ((mf >> 6) + ky) * 58 + (mf & 63) + kx + g;
            const int w0 = (s * 8 + tig) * 232 + pos0;
            uint32_t ah[4];
            ah[0] = slabh[w0];
            ah[1] = slabh[w0 + 8];
            ah[2] = slabh[w0 + 4 * 232];
            ah[3] = slabh[w0 + 4 * 232 + 8];

            const uint32_t sbb = cur + (uint32_t)(s * 2048);
#pragma unroll
            for (int np = 0; np < 2; np++) {
                uint32_t bh[4];
                ldsm4t(bh, sbb + bnp[np]);
                mma16816(acc[np * 2],     ah, bh[0], bh[1]);
                mma16816(acc[np * 2 + 1], ah, bh[2], bh[3]);
            }
        }
    }

    // ---- epilogue: register accumulators -> gmem ----
    {
        const int y = r0 + (mf >> 6);
        const int xa = (mf & 63) + g;     // <= 55, always valid
        const int xb = xa + 8;
#pragma unroll
        for (int ni = 0; ni < 4; ni++) {
            const int n = nh * 64 + nw * 32 + ni * 8 + tig * 2;
            float* p = out + ((size_t)b * COUT + n) * (HW * HW) + y * HW;
            p[xa] = acc[ni][0];
            p[HW * HW + xa] = acc[ni][1];
            if (xb < HW) {
                p[xb] = acc[ni][2];
                p[HW * HW + xb] = acc[ni][3];
            }
        }
    }
}

// ================= launcher =================
extern "C" void kernel_launch(void* const* d_in, const int* in_sizes, int n_in,
                              void* d_out, int out_size) {
    const float* x = (const float*)d_in[0];        // [32,128,56,56]
    const float* w = (const float*)d_in[1];        // [5,128,128,3,3]
    const float* scales = (const float*)d_in[2];   // [5]
    float* out = (float*)d_out;                    // [32,128,56,56]

    cudaFuncSetAttribute(conv_kernel, cudaFuncAttributeMaxDynamicSharedMemorySize,
                         SMEM_TOTAL);

    mean_abs_part_kernel<<<160, 256>>>(w);
    build_wB_kernel<<<32, 256>>>(w, scales);
    conv_kernel<<<dim3(28, 32, 2), 512, SMEM_TOTAL>>>(x, out);
}